// round 16
// baseline (speedup 1.0000x reference)
#include <cuda_runtime.h>

#define NSEG 256
#define DDIM 256
#define TPB  256
#define MAXN 4096   // key scratch capacity (N=2048 here)
#define SPLIT 2     // chunks per protein: best measured accumulate (R14)

// Written by pre-kernel block 0 each call (no zero-init needed — overwritten).
__device__ int   g_keys[MAXN];    // keys converted to int32
__device__ float g_scale[NSEG];   // 1 / (count_b * L)

// ---------------------------------------------------------------------------
// Kernel A: zero d_out (poisoned by harness); block 0 additionally converts
// keys and builds the per-segment scale table. Fully hidden under the
// accumulate kernel's stream via PDL.
//
// Key dtype detect: viewing the buffer as int32 words, int64 values < 256
// have all-zero odd words within the first nkeys words, while sorted int32
// keys reach nonzero values at odd indices.
__global__ void __launch_bounds__(TPB) pp_pre_kernel(
    const int* __restrict__ kwords,    // keys viewed as int32 words
    float4* __restrict__ out4,         // d_out as float4
    int nout4, int nkeys, float Lf)
{
    int i = blockIdx.x * blockDim.x + threadIdx.x;
    if (i < nout4) out4[i] = make_float4(0.f, 0.f, 0.f, 0.f);

    if (blockIdx.x == 0) {
        const int tid = threadIdx.x;
        __shared__ int hist[NSEG];
        hist[tid] = 0;

        // dtype detect
        int local = 0;
        for (int k = tid; k < nkeys; k += TPB)
            if ((k & 1) && kwords[k] != 0) local = 1;
        const int is32 = __syncthreads_or(local);

        // convert keys + histogram counts (smem atomics)
        for (int n = tid; n < nkeys; n += TPB) {
            int key = is32 ? kwords[n] : kwords[2 * n];   // int64 lo word
            key &= (NSEG - 1);                            // never OOB
            g_keys[n] = key;
            atomicAdd(&hist[key], 1);
        }
        __syncthreads();

        int c = hist[tid];
        g_scale[tid] = __fdividef(1.0f, (float)(c > 0 ? c : 1) * Lf);
    }
}

// ---------------------------------------------------------------------------
// Kernel B: one block per protein CHUNK (SPLIT=2, grid=2N — best measured
// DRAM-active 91.0%). Launched with PDL: starts while pp_pre_kernel is in
// flight; cudaGridDependencySynchronize() sits AFTER the independent
// streaming loop, so the pre-kernel + launch gap hide fully.
//
// Stream: each thread strides float4s of its half-protein slice (coalesced
// 128B transactions), unroll 8 for deeper MLP during wave ramps. Stride 256
// over 64 float4s/row keeps each thread in column group (tid % 64).
//
// Epilogue (widened vs R14): ALL 256 threads participate — thread t folds
// the 4 partial copies of scalar column t from smem and issues exactly ONE
// pre-scaled atomicAdd. Per-block atomic phase shrinks ~4x vs 64 threads x 4
// serialized REDGs.
__global__ void __launch_bounds__(TPB) pp_accum_kernel(
    const float4* __restrict__ in,       // [N, L*D/4]
    float* __restrict__ out,             // [NSEG, DDIM]
    int vec_per_protein)                 // L*D/4
{
    __shared__ float4 sm4[TPB];
    const int chunk = blockIdx.x;
    const int n     = chunk / SPLIT;       // protein
    const int c     = chunk % SPLIT;       // chunk within protein
    const int tid   = threadIdx.x;
    const int vec_per_chunk = vec_per_protein / SPLIT;

    const float4* base = in + (size_t)n * (size_t)vec_per_protein
                            + (size_t)c * (size_t)vec_per_chunk;
    float4 acc = make_float4(0.f, 0.f, 0.f, 0.f);
    #pragma unroll 8
    for (int idx = tid; idx < vec_per_chunk; idx += TPB) {
        float4 v = base[idx];
        acc.x += v.x; acc.y += v.y; acc.z += v.z; acc.w += v.w;
    }
    sm4[tid] = acc;

    // Wait for pp_pre_kernel completion (PDL) before touching its outputs.
    cudaGridDependencySynchronize();
    __syncthreads();

    const int   b     = g_keys[n];
    const float scale = g_scale[b];

    // Full-width fold: column d (0..255) lives at sm4-lane (d>>2)+64k,
    // component (d&3), for k = 0..3.
    const float* smf = (const float*)sm4;
    const int lane = (tid >> 2);          // float4 slot within group of 64
    const int comp = (tid & 3);           // component within float4
    float s = smf[(lane      ) * 4 + comp]
            + smf[(lane +  64) * 4 + comp]
            + smf[(lane + 128) * 4 + comp]
            + smf[(lane + 192) * 4 + comp];
    atomicAdd(out + b * DDIM + tid, s * scale);
}

// ---------------------------------------------------------------------------
extern "C" void kernel_launch(void* const* d_in, const int* in_sizes, int n_in,
                              void* d_out, int out_size) {
    // Pick embeds by element count (defend against input-order surprises).
    int ei = 0, ki = 1;
    if (n_in >= 2 && in_sizes[1] > in_sizes[0]) { ei = 1; ki = 0; }

    const float* embeds = (const float*)d_in[ei];   // [N, L, D] fp32
    const int*   kwords = (const int*)d_in[ki];     // [N] int32 or int64 (words)

    const int N            = in_sizes[ki];
    const int per_protein  = in_sizes[ei] / N;      // L * D
    const int L            = per_protein / DDIM;    // sequence length
    const int vec_per_prot = per_protein / 4;
    const int nout4        = out_size / 4;

    pp_pre_kernel<<<(nout4 + TPB - 1) / TPB, TPB>>>(
        kwords, (float4*)d_out, nout4, N, (float)L);

    // Accumulate with programmatic dependent launch: overlaps the pre-kernel.
    cudaLaunchConfig_t cfg = {};
    cfg.gridDim  = dim3((unsigned)(N * SPLIT), 1, 1);
    cfg.blockDim = dim3(TPB, 1, 1);
    cudaLaunchAttribute attrs[1];
    attrs[0].id = cudaLaunchAttributeProgrammaticStreamSerialization;
    attrs[0].val.programmaticStreamSerializationAllowed = 1;
    cfg.attrs    = attrs;
    cfg.numAttrs = 1;
    cudaLaunchKernelEx(&cfg, pp_accum_kernel,
                       (const float4*)embeds, (float*)d_out, vec_per_prot);
}